// round 1
// baseline (speedup 1.0000x reference)
#include <cuda_runtime.h>

// Problem constants
static constexpr int Bc     = 8;
static constexpr int Nc     = 4096;
static constexpr int DIMc   = 512;
static constexpr int HEADSc = 8;
static constexpr int DHEADc = 64;
static constexpr int QKVc   = 1536;     // 3 * HEADS * DHEAD
static constexpr int MTOTc  = Bc * Nc;  // 32768

// Scratch (device globals: no allocations allowed in kernel_launch)
__device__ float g_qkv [(size_t)MTOTc * QKVc];   // (B*N, 1536)  q|k|v
__device__ float g_attn[(size_t)MTOTc * DIMc];   // (B*N, 512)   attention output (head-merged)

// ---------------------------------------------------------------------------
// Classic register-blocked SGEMM: C[m][n] = sum_k A[m][k] * W[n][k] (+ bias[n])
// A: (M,K) row-major, W: (Nn,K) row-major. All dims multiples of tile sizes.
// BM=BN=128, BK=16, 256 threads, 8x8 per-thread micro-tile.
// ---------------------------------------------------------------------------
template<bool BIAS>
__global__ __launch_bounds__(256)
void sgemm_nt(const float* __restrict__ A, const float* __restrict__ W,
              const float* __restrict__ bias, float* __restrict__ C,
              int M, int Nn, int K)
{
    constexpr int BM = 128, BN = 128, BK = 16, TM = 8, TN = 8;
    __shared__ float As[BK][BM + 4];
    __shared__ float Bs[BK][BN + 4];

    const int tid = threadIdx.x;
    const int tx  = tid & 15;   // 0..15  (N direction)
    const int ty  = tid >> 4;   // 0..15  (M direction)

    const float* Ab = A + (size_t)blockIdx.y * BM * K;
    const float* Wb = W + (size_t)blockIdx.x * BN * K;

    float acc[TM][TN];
    #pragma unroll
    for (int i = 0; i < TM; i++)
        #pragma unroll
        for (int j = 0; j < TN; j++) acc[i][j] = 0.f;

    for (int k0 = 0; k0 < K; k0 += BK) {
        // Load 128x16 tiles of A and W (512 float4 each, 2 per thread)
        #pragma unroll
        for (int l = 0; l < 2; l++) {
            int li   = tid + l * 256;     // 0..511
            int row  = li >> 2;           // 0..127
            int col4 = (li & 3) << 2;     // 0,4,8,12
            float4 a4 = *(const float4*)(Ab + (size_t)row * K + k0 + col4);
            As[col4 + 0][row] = a4.x;
            As[col4 + 1][row] = a4.y;
            As[col4 + 2][row] = a4.z;
            As[col4 + 3][row] = a4.w;
            float4 b4 = *(const float4*)(Wb + (size_t)row * K + k0 + col4);
            Bs[col4 + 0][row] = b4.x;
            Bs[col4 + 1][row] = b4.y;
            Bs[col4 + 2][row] = b4.z;
            Bs[col4 + 3][row] = b4.w;
        }
        __syncthreads();

        #pragma unroll
        for (int k = 0; k < BK; k++) {
            float ar[TM], br[TN];
            #pragma unroll
            for (int i = 0; i < TM; i++) ar[i] = As[k][ty * TM + i];
            #pragma unroll
            for (int j = 0; j < TN; j++) br[j] = Bs[k][tx * TN + j];
            #pragma unroll
            for (int i = 0; i < TM; i++)
                #pragma unroll
                for (int j = 0; j < TN; j++)
                    acc[i][j] = fmaf(ar[i], br[j], acc[i][j]);
        }
        __syncthreads();
    }

    // Epilogue
    #pragma unroll
    for (int i = 0; i < TM; i++) {
        int m = blockIdx.y * BM + ty * TM + i;
        int n0 = blockIdx.x * BN + tx * TN;
        float* Cr = C + (size_t)m * Nn + n0;
        #pragma unroll
        for (int j = 0; j < TN; j += 4) {
            float4 v;
            v.x = acc[i][j + 0];
            v.y = acc[i][j + 1];
            v.z = acc[i][j + 2];
            v.w = acc[i][j + 3];
            if (BIAS) {
                v.x += bias[n0 + j + 0];
                v.y += bias[n0 + j + 1];
                v.z += bias[n0 + j + 2];
                v.w += bias[n0 + j + 3];
            }
            *(float4*)(Cr + j) = v;
        }
    }
}

// ---------------------------------------------------------------------------
// Block-diagonal attention: one CTA per 16-token group.
// Group id -> (b, h, a, m); token g = i*4+j maps to seq n = (a*4+i)*512 + m*4+j
// q/k/v columns in g_qkv row: h*64+d, 512+h*64+d, 1024+h*64+d
// ---------------------------------------------------------------------------
__global__ __launch_bounds__(256)
void diag_attn_kernel()
{
    __shared__ float qs[16][65];
    __shared__ float ks[16][65];
    __shared__ float vs[16][65];
    __shared__ float pr[16][17];

    const int gid = blockIdx.x;           // 0..16383
    const int m   = gid & 127;
    const int a   = (gid >> 7) & 1;
    const int h   = (gid >> 8) & 7;
    const int b   = gid >> 11;
    const int tid = threadIdx.x;

    // Load q, k, v tiles (16 tokens x 64 dims each)
    for (int e = tid; e < 1024; e += 256) {
        int tok = e >> 6, d = e & 63;
        int i = tok >> 2, j = tok & 3;
        int n = (a * 4 + i) * 512 + m * 4 + j;
        size_t row = (size_t)(b * Nc + n) * QKVc;
        int col = h * 64 + d;
        qs[tok][d] = g_qkv[row + col];
        ks[tok][d] = g_qkv[row + 512 + col];
        vs[tok][d] = g_qkv[row + 1024 + col];
    }
    __syncthreads();

    // dots: 256 threads, one (x,y) entry each
    {
        int x = tid >> 4, y = tid & 15;
        float s = 0.f;
        #pragma unroll
        for (int d = 0; d < 64; d++) s = fmaf(qs[x][d], ks[y][d], s);
        pr[x][y] = s * 0.125f;   // SCALE = 1/sqrt(64)
    }
    __syncthreads();

    // softmax per row (16 threads)
    if (tid < 16) {
        float mx = pr[tid][0];
        #pragma unroll
        for (int y = 1; y < 16; y++) mx = fmaxf(mx, pr[tid][y]);
        float ex[16];
        float sum = 0.f;
        #pragma unroll
        for (int y = 0; y < 16; y++) { ex[y] = __expf(pr[tid][y] - mx); sum += ex[y]; }
        float inv = 1.f / sum;
        #pragma unroll
        for (int y = 0; y < 16; y++) pr[tid][y] = ex[y] * inv;
    }
    __syncthreads();

    // out = P @ V, scatter back to (b, n, h*64+d) layout
    for (int e = tid; e < 1024; e += 256) {
        int tok = e >> 6, d = e & 63;
        float o = 0.f;
        #pragma unroll
        for (int y = 0; y < 16; y++) o = fmaf(pr[tok][y], vs[y][d], o);
        int i = tok >> 2, j = tok & 3;
        int n = (a * 4 + i) * 512 + m * 4 + j;
        g_attn[(size_t)(b * Nc + n) * DIMc + h * 64 + d] = o;
    }
}

// ---------------------------------------------------------------------------
extern "C" void kernel_launch(void* const* d_in, const int* in_sizes, int n_in,
                              void* d_out, int out_size)
{
    const float* x     = (const float*)d_in[0];   // (8, 4096, 512)
    const float* w_qkv = (const float*)d_in[1];   // (1536, 512)
    const float* w_out = (const float*)d_in[2];   // (512, 512)
    const float* b_out = (const float*)d_in[3];   // (512,)
    float* out = (float*)d_out;                   // (8, 4096, 512)

    float* qkv  = nullptr;
    float* attn = nullptr;
    cudaGetSymbolAddress((void**)&qkv,  g_qkv);
    cudaGetSymbolAddress((void**)&attn, g_attn);

    // GEMM1: qkv = x @ w_qkv^T   (32768 x 1536 x 512)
    {
        dim3 grid(QKVc / 128, MTOTc / 128);
        sgemm_nt<false><<<grid, 256>>>(x, w_qkv, nullptr, qkv, MTOTc, QKVc, DIMc);
    }

    // Attention: 16384 independent 16x16x64 blocks
    diag_attn_kernel<<<16384, 256>>>();

    // GEMM2: out = attn @ w_out^T + b_out   (32768 x 512 x 512)
    {
        dim3 grid(DIMc / 128, MTOTc / 128);
        sgemm_nt<true><<<grid, 256>>>(attn, w_out, b_out, out, MTOTc, DIMc, DIMc);
    }
}

// round 5
// speedup vs baseline: 2.4312x; 2.4312x over previous
#include <cuda_runtime.h>
#include <cstdint>

// Problem constants
static constexpr int Bc     = 8;
static constexpr int Nc     = 4096;
static constexpr int DIMc   = 512;
static constexpr int QKVc   = 1536;     // 3 * HEADS * DHEAD
static constexpr int MTOTc  = Bc * Nc;  // 32768

// Scratch (device globals: no allocations allowed)
__device__ float g_qkv [(size_t)MTOTc * QKVc];   // GEMM1 out (fp32) q|k|v
__device__ float g_attn[(size_t)MTOTc * DIMc];   // attention out (fp32)

__device__ __forceinline__ uint32_t tf32_bits(float x) {
    uint32_t u;
    asm("cvt.rna.tf32.f32 %0, %1;" : "=r"(u) : "f"(x));
    return u;
}

// ---------------------------------------------------------------------------
// TF32 tensor-core GEMM: C[m][n] = sum_k A[m][k]*W[n][k] (+ bias)
// A:(M,K) row-major fp32, W:(Nn,K) row-major fp32; fragments rounded to tf32
// (RNA) in-register before each MMA.
// CTA tile 128x128, BK=16, 8 warps (4x2), warp tile 32x64, mma m16n8k8.
// Double-buffered smem via cp.async.
// ---------------------------------------------------------------------------
template<bool BIAS>
__global__ __launch_bounds__(256)
void gemm_tf32(const float* __restrict__ A, const float* __restrict__ W,
               const float* __restrict__ bias, float* __restrict__ C,
               int M, int Nn, int K)
{
    constexpr int BK = 16;
    constexpr int LDS_STRIDE = 20;   // floats; 80B rows -> 16B aligned, conflict-free frags
    __shared__ float As[2][128][LDS_STRIDE];
    __shared__ float Ws[2][128][LDS_STRIDE];

    const int tid  = threadIdx.x;
    const int lane = tid & 31;
    const int wid  = tid >> 5;
    const int wm   = wid >> 1;        // 0..3
    const int wn   = wid & 1;         // 0..1
    const int g    = lane >> 2;       // groupID 0..7
    const int tg   = lane & 3;        // threadInGroup 0..3

    const int m0 = blockIdx.y * 128;
    const int n0 = blockIdx.x * 128;

    const float* Ab = A + (size_t)m0 * K;
    const float* Wb = W + (size_t)n0 * K;

    // per-thread staging coords: 2 16B chunks per matrix per tile
    const int ldrow0 = tid >> 2;            // 0..63
    const int ldc4   = (tid & 3) << 2;      // 0,4,8,12

    auto stage = [&](int buf, int k0) {
        #pragma unroll
        for (int l = 0; l < 2; l++) {
            int row = ldrow0 + l * 64;
            uint32_t da = (uint32_t)__cvta_generic_to_shared(&As[buf][row][ldc4]);
            const float* sa = Ab + (size_t)row * K + k0 + ldc4;
            asm volatile("cp.async.cg.shared.global [%0], [%1], 16;\n" :: "r"(da), "l"(sa));
            uint32_t dw = (uint32_t)__cvta_generic_to_shared(&Ws[buf][row][ldc4]);
            const float* sw = Wb + (size_t)row * K + k0 + ldc4;
            asm volatile("cp.async.cg.shared.global [%0], [%1], 16;\n" :: "r"(dw), "l"(sw));
        }
        asm volatile("cp.async.commit_group;\n");
    };

    float c[2][8][4];
    #pragma unroll
    for (int mt = 0; mt < 2; mt++)
        #pragma unroll
        for (int nt = 0; nt < 8; nt++)
            #pragma unroll
            for (int r = 0; r < 4; r++) c[mt][nt][r] = 0.f;

    stage(0, 0);
    const int KT = K / BK;
    int buf = 0;

    for (int kt = 0; kt < KT; kt++) {
        asm volatile("cp.async.wait_group 0;\n");
        __syncthreads();
        if (kt + 1 < KT) stage(buf ^ 1, (kt + 1) * BK);

        #pragma unroll
        for (int ks = 0; ks < 2; ks++) {
            const int kb = ks * 8;
            uint32_t a[2][4];
            #pragma unroll
            for (int mt = 0; mt < 2; mt++) {
                int row = wm * 32 + mt * 16;
                a[mt][0] = tf32_bits(As[buf][row + g    ][kb + tg    ]);
                a[mt][1] = tf32_bits(As[buf][row + g + 8][kb + tg    ]);
                a[mt][2] = tf32_bits(As[buf][row + g    ][kb + tg + 4]);
                a[mt][3] = tf32_bits(As[buf][row + g + 8][kb + tg + 4]);
            }
            uint32_t b[8][2];
            #pragma unroll
            for (int nt = 0; nt < 8; nt++) {
                int n = wn * 64 + nt * 8 + g;
                b[nt][0] = tf32_bits(Ws[buf][n][kb + tg    ]);
                b[nt][1] = tf32_bits(Ws[buf][n][kb + tg + 4]);
            }
            #pragma unroll
            for (int mt = 0; mt < 2; mt++)
                #pragma unroll
                for (int nt = 0; nt < 8; nt++) {
                    asm volatile(
                        "mma.sync.aligned.m16n8k8.row.col.f32.tf32.tf32.f32 "
                        "{%0,%1,%2,%3}, {%4,%5,%6,%7}, {%8,%9}, {%0,%1,%2,%3};"
                        : "+f"(c[mt][nt][0]), "+f"(c[mt][nt][1]),
                          "+f"(c[mt][nt][2]), "+f"(c[mt][nt][3])
                        : "r"(a[mt][0]), "r"(a[mt][1]), "r"(a[mt][2]), "r"(a[mt][3]),
                          "r"(b[nt][0]), "r"(b[nt][1]));
                }
        }
        __syncthreads();
        buf ^= 1;
    }

    // Epilogue: c0,c1 at (g, 2tg), c2,c3 at (g+8, 2tg)
    #pragma unroll
    for (int mt = 0; mt < 2; mt++) {
        int row = m0 + wm * 32 + mt * 16 + g;
        #pragma unroll
        for (int nt = 0; nt < 8; nt++) {
            int col = n0 + wn * 64 + nt * 8 + 2 * tg;
            float bx = 0.f, by = 0.f;
            if (BIAS) { bx = bias[col]; by = bias[col + 1]; }
            float2 v0 = make_float2(c[mt][nt][0] + bx, c[mt][nt][1] + by);
            float2 v1 = make_float2(c[mt][nt][2] + bx, c[mt][nt][3] + by);
            *(float2*)(C + (size_t)row * Nn + col)       = v0;
            *(float2*)(C + (size_t)(row + 8) * Nn + col) = v1;
        }
    }
}

// ---------------------------------------------------------------------------
// Block-diagonal attention: one CTA per 16-token group (fp32).
// ---------------------------------------------------------------------------
__global__ __launch_bounds__(256)
void diag_attn_kernel()
{
    __shared__ float qs[16][65];
    __shared__ float ks[16][65];
    __shared__ float vs[16][65];
    __shared__ float pr[16][17];

    const int gid = blockIdx.x;           // 0..16383
    const int m   = gid & 127;
    const int a   = (gid >> 7) & 1;
    const int h   = (gid >> 8) & 7;
    const int b   = gid >> 11;
    const int tid = threadIdx.x;

    for (int e = tid; e < 1024; e += 256) {
        int tok = e >> 6, d = e & 63;
        int i = tok >> 2, j = tok & 3;
        int n = (a * 4 + i) * 512 + m * 4 + j;
        size_t row = (size_t)(b * Nc + n) * QKVc;
        int col = h * 64 + d;
        qs[tok][d] = g_qkv[row + col];
        ks[tok][d] = g_qkv[row + 512 + col];
        vs[tok][d] = g_qkv[row + 1024 + col];
    }
    __syncthreads();

    {
        int x = tid >> 4, y = tid & 15;
        float s = 0.f;
        #pragma unroll
        for (int d = 0; d < 64; d++) s = fmaf(qs[x][d], ks[y][d], s);
        pr[x][y] = s * 0.125f;
    }
    __syncthreads();

    if (tid < 16) {
        float mx = pr[tid][0];
        #pragma unroll
        for (int y = 1; y < 16; y++) mx = fmaxf(mx, pr[tid][y]);
        float ex[16];
        float sum = 0.f;
        #pragma unroll
        for (int y = 0; y < 16; y++) { ex[y] = __expf(pr[tid][y] - mx); sum += ex[y]; }
        float inv = 1.f / sum;
        #pragma unroll
        for (int y = 0; y < 16; y++) pr[tid][y] = ex[y] * inv;
    }
    __syncthreads();

    for (int e = tid; e < 1024; e += 256) {
        int tok = e >> 6, d = e & 63;
        float o = 0.f;
        #pragma unroll
        for (int y = 0; y < 16; y++) o = fmaf(pr[tok][y], vs[y][d], o);
        int i = tok >> 2, j = tok & 3;
        int n = (a * 4 + i) * 512 + m * 4 + j;
        g_attn[(size_t)(b * Nc + n) * DIMc + h * 64 + d] = o;
    }
}

// ---------------------------------------------------------------------------
extern "C" void kernel_launch(void* const* d_in, const int* in_sizes, int n_in,
                              void* d_out, int out_size)
{
    const float* x     = (const float*)d_in[0];   // (8, 4096, 512)
    const float* w_qkv = (const float*)d_in[1];   // (1536, 512)
    const float* w_out = (const float*)d_in[2];   // (512, 512)
    const float* b_out = (const float*)d_in[3];   // (512,)
    float* out = (float*)d_out;

    float *qkv, *attn;
    cudaGetSymbolAddress((void**)&qkv,  g_qkv);
    cudaGetSymbolAddress((void**)&attn, g_attn);

    // GEMM1: qkv = x @ w_qkv^T   (32768 x 1536 x 512)
    {
        dim3 grid(QKVc / 128, MTOTc / 128);
        gemm_tf32<false><<<grid, 256>>>(x, w_qkv, nullptr, qkv, MTOTc, QKVc, DIMc);
    }

    // Attention: 16384 independent 16x16x64 blocks
    diag_attn_kernel<<<16384, 256>>>();

    // GEMM2: out = attn @ w_out^T + b_out  (32768 x 512 x 512)
    {
        dim3 grid(DIMc / 128, MTOTc / 128);
        gemm_tf32<true><<<grid, 256>>>(attn, w_out, b_out, out, MTOTc, DIMc, DIMc);
    }
}

// round 6
// speedup vs baseline: 2.4549x; 1.0097x over previous
#include <cuda_runtime.h>
#include <cstdint>

// Problem constants
static constexpr int Bc     = 8;
static constexpr int Nc     = 4096;
static constexpr int DIMc   = 512;
static constexpr int QKVc   = 1536;     // 3 * HEADS * DHEAD
static constexpr int MTOTc  = Bc * Nc;  // 32768

// Scratch (device globals: no allocations allowed)
__device__ float g_qkv [(size_t)MTOTc * QKVc];   // GEMM1 out (fp32) q|k|v
__device__ float g_attn[(size_t)MTOTc * DIMc];   // attention out (fp32)

__device__ __forceinline__ uint32_t tf32_bits(float x) {
    uint32_t u;
    asm("cvt.rna.tf32.f32 %0, %1;" : "=r"(u) : "f"(x));
    return u;
}

// ---------------------------------------------------------------------------
// TF32 tensor-core GEMM: C[m][n] = sum_k A[m][k]*W[n][k] (+ bias)
// A:(M,K) row-major fp32, W:(Nn,K) row-major fp32; fragments rounded to tf32
// (RNA) in-register before each MMA.
// CTA tile 128x128, BK=16, 8 warps (4x2), warp tile 32x64, mma m16n8k8.
// 4-stage cp.async ring (wait_group 2 -> 3 tiles in flight).
// ---------------------------------------------------------------------------
static constexpr int STAGES = 4;
static constexpr int LDS_STRIDE = 20;   // floats; 80B rows: 16B-aligned, conflict-free
static constexpr int TILE_FLOATS = 128 * LDS_STRIDE;        // per matrix per stage
static constexpr int GEMM_SMEM_BYTES = 2 * STAGES * TILE_FLOATS * 4;   // 81920

template<bool BIAS>
__global__ __launch_bounds__(256)
void gemm_tf32(const float* __restrict__ A, const float* __restrict__ W,
               const float* __restrict__ bias, float* __restrict__ C,
               int M, int Nn, int K)
{
    constexpr int BK = 16;
    extern __shared__ float smem[];
    float (*As)[128][LDS_STRIDE] = (float (*)[128][LDS_STRIDE])smem;
    float (*Ws)[128][LDS_STRIDE] = (float (*)[128][LDS_STRIDE])(smem + STAGES * TILE_FLOATS);

    const int tid  = threadIdx.x;
    const int lane = tid & 31;
    const int wid  = tid >> 5;
    const int wm   = wid >> 1;        // 0..3
    const int wn   = wid & 1;         // 0..1
    const int g    = lane >> 2;       // groupID 0..7
    const int tg   = lane & 3;        // threadInGroup 0..3

    const int m0 = blockIdx.y * 128;
    const int n0 = blockIdx.x * 128;

    const float* Ab = A + (size_t)m0 * K;
    const float* Wb = W + (size_t)n0 * K;

    // per-thread staging coords: 2 16B chunks per matrix per tile
    const int ldrow0 = tid >> 2;            // 0..63
    const int ldc4   = (tid & 3) << 2;      // 0,4,8,12

    auto stage = [&](int buf, int k0) {
        #pragma unroll
        for (int l = 0; l < 2; l++) {
            int row = ldrow0 + l * 64;
            uint32_t da = (uint32_t)__cvta_generic_to_shared(&As[buf][row][ldc4]);
            const float* sa = Ab + (size_t)row * K + k0 + ldc4;
            asm volatile("cp.async.cg.shared.global [%0], [%1], 16;\n" :: "r"(da), "l"(sa));
            uint32_t dw = (uint32_t)__cvta_generic_to_shared(&Ws[buf][row][ldc4]);
            const float* sw = Wb + (size_t)row * K + k0 + ldc4;
            asm volatile("cp.async.cg.shared.global [%0], [%1], 16;\n" :: "r"(dw), "l"(sw));
        }
        asm volatile("cp.async.commit_group;\n");
    };

    float c[2][8][4];
    #pragma unroll
    for (int mt = 0; mt < 2; mt++)
        #pragma unroll
        for (int nt = 0; nt < 8; nt++)
            #pragma unroll
            for (int r = 0; r < 4; r++) c[mt][nt][r] = 0.f;

    const int KT = K / BK;   // 32 or 96
    // Prefill 3 stages
    stage(0, 0);
    stage(1, BK);
    stage(2, 2 * BK);

    for (int kt = 0; kt < KT; kt++) {
        // stage kt is the oldest of the (up to 3) pending groups
        asm volatile("cp.async.wait_group 2;\n");
        __syncthreads();   // data visible to all; all warps done reading stage kt-1

        if (kt + 3 < KT) stage((kt + 3) & (STAGES - 1), (kt + 3) * BK);

        const int buf = kt & (STAGES - 1);
        #pragma unroll
        for (int ks = 0; ks < 2; ks++) {
            const int kb = ks * 8;
            uint32_t a[2][4];
            #pragma unroll
            for (int mt = 0; mt < 2; mt++) {
                int row = wm * 32 + mt * 16;
                a[mt][0] = tf32_bits(As[buf][row + g    ][kb + tg    ]);
                a[mt][1] = tf32_bits(As[buf][row + g + 8][kb + tg    ]);
                a[mt][2] = tf32_bits(As[buf][row + g    ][kb + tg + 4]);
                a[mt][3] = tf32_bits(As[buf][row + g + 8][kb + tg + 4]);
            }
            uint32_t b[8][2];
            #pragma unroll
            for (int nt = 0; nt < 8; nt++) {
                int n = wn * 64 + nt * 8 + g;
                b[nt][0] = tf32_bits(Ws[buf][n][kb + tg    ]);
                b[nt][1] = tf32_bits(Ws[buf][n][kb + tg + 4]);
            }
            #pragma unroll
            for (int mt = 0; mt < 2; mt++)
                #pragma unroll
                for (int nt = 0; nt < 8; nt++) {
                    asm volatile(
                        "mma.sync.aligned.m16n8k8.row.col.f32.tf32.tf32.f32 "
                        "{%0,%1,%2,%3}, {%4,%5,%6,%7}, {%8,%9}, {%0,%1,%2,%3};"
                        : "+f"(c[mt][nt][0]), "+f"(c[mt][nt][1]),
                          "+f"(c[mt][nt][2]), "+f"(c[mt][nt][3])
                        : "r"(a[mt][0]), "r"(a[mt][1]), "r"(a[mt][2]), "r"(a[mt][3]),
                          "r"(b[nt][0]), "r"(b[nt][1]));
                }
        }
    }

    // Epilogue: c0,c1 at (g, 2tg), c2,c3 at (g+8, 2tg)
    #pragma unroll
    for (int mt = 0; mt < 2; mt++) {
        int row = m0 + wm * 32 + mt * 16 + g;
        #pragma unroll
        for (int nt = 0; nt < 8; nt++) {
            int col = n0 + wn * 64 + nt * 8 + 2 * tg;
            float bx = 0.f, by = 0.f;
            if (BIAS) { bx = bias[col]; by = bias[col + 1]; }
            float2 v0 = make_float2(c[mt][nt][0] + bx, c[mt][nt][1] + by);
            float2 v1 = make_float2(c[mt][nt][2] + bx, c[mt][nt][3] + by);
            *(float2*)(C + (size_t)row * Nn + col)       = v0;
            *(float2*)(C + (size_t)(row + 8) * Nn + col) = v1;
        }
    }
}

// ---------------------------------------------------------------------------
// Block-diagonal attention: one CTA per 16-token group (fp32).
// ---------------------------------------------------------------------------
__global__ __launch_bounds__(256)
void diag_attn_kernel()
{
    __shared__ float qs[16][65];
    __shared__ float ks[16][65];
    __shared__ float vs[16][65];
    __shared__ float pr[16][17];

    const int gid = blockIdx.x;           // 0..16383
    const int m   = gid & 127;
    const int a   = (gid >> 7) & 1;
    const int h   = (gid >> 8) & 7;
    const int b   = gid >> 11;
    const int tid = threadIdx.x;

    for (int e = tid; e < 1024; e += 256) {
        int tok = e >> 6, d = e & 63;
        int i = tok >> 2, j = tok & 3;
        int n = (a * 4 + i) * 512 + m * 4 + j;
        size_t row = (size_t)(b * Nc + n) * QKVc;
        int col = h * 64 + d;
        qs[tok][d] = g_qkv[row + col];
        ks[tok][d] = g_qkv[row + 512 + col];
        vs[tok][d] = g_qkv[row + 1024 + col];
    }
    __syncthreads();

    {
        int x = tid >> 4, y = tid & 15;
        float s = 0.f;
        #pragma unroll
        for (int d = 0; d < 64; d++) s = fmaf(qs[x][d], ks[y][d], s);
        pr[x][y] = s * 0.125f;
    }
    __syncthreads();

    if (tid < 16) {
        float mx = pr[tid][0];
        #pragma unroll
        for (int y = 1; y < 16; y++) mx = fmaxf(mx, pr[tid][y]);
        float ex[16];
        float sum = 0.f;
        #pragma unroll
        for (int y = 0; y < 16; y++) { ex[y] = __expf(pr[tid][y] - mx); sum += ex[y]; }
        float inv = 1.f / sum;
        #pragma unroll
        for (int y = 0; y < 16; y++) pr[tid][y] = ex[y] * inv;
    }
    __syncthreads();

    for (int e = tid; e < 1024; e += 256) {
        int tok = e >> 6, d = e & 63;
        float o = 0.f;
        #pragma unroll
        for (int y = 0; y < 16; y++) o = fmaf(pr[tok][y], vs[y][d], o);
        int i = tok >> 2, j = tok & 3;
        int n = (a * 4 + i) * 512 + m * 4 + j;
        g_attn[(size_t)(b * Nc + n) * DIMc + h * 64 + d] = o;
    }
}

// ---------------------------------------------------------------------------
extern "C" void kernel_launch(void* const* d_in, const int* in_sizes, int n_in,
                              void* d_out, int out_size)
{
    const float* x     = (const float*)d_in[0];   // (8, 4096, 512)
    const float* w_qkv = (const float*)d_in[1];   // (1536, 512)
    const float* w_out = (const float*)d_in[2];   // (512, 512)
    const float* b_out = (const float*)d_in[3];   // (512,)
    float* out = (float*)d_out;

    float *qkv, *attn;
    cudaGetSymbolAddress((void**)&qkv,  g_qkv);
    cudaGetSymbolAddress((void**)&attn, g_attn);

    // Opt in to 80KB dynamic smem (idempotent)
    cudaFuncSetAttribute(gemm_tf32<false>,
                         cudaFuncAttributeMaxDynamicSharedMemorySize, GEMM_SMEM_BYTES);
    cudaFuncSetAttribute(gemm_tf32<true>,
                         cudaFuncAttributeMaxDynamicSharedMemorySize, GEMM_SMEM_BYTES);

    // GEMM1: qkv = x @ w_qkv^T   (32768 x 1536 x 512)
    {
        dim3 grid(QKVc / 128, MTOTc / 128);
        gemm_tf32<false><<<grid, 256, GEMM_SMEM_BYTES>>>(x, w_qkv, nullptr, qkv,
                                                         MTOTc, QKVc, DIMc);
    }

    // Attention: 16384 independent 16x16x64 blocks
    diag_attn_kernel<<<16384, 256>>>();

    // GEMM2: out = attn @ w_out^T + b_out  (32768 x 512 x 512)
    {
        dim3 grid(DIMc / 128, MTOTc / 128);
        gemm_tf32<true><<<grid, 256, GEMM_SMEM_BYTES>>>(attn, w_out, b_out, out,
                                                        MTOTc, DIMc, DIMc);
    }
}